// round 2
// baseline (speedup 1.0000x reference)
#include <cuda_runtime.h>
#include <stdint.h>

// ======================= device globals (scratch; no allocs) =======================
__device__ unsigned int g_over_cnt;
__device__ unsigned int g_under_cnt;
__device__ float4       g_qparams;   // {sigma, 1/sigma, t_min, t_max}

// ======================= threefry2x32 (20 rounds, Random123/JAX) ===================
// Counter is (0, ctr) since N < 2^32; returns o0 ^ o1 (JAX partitionable 32-bit bits).
__device__ __forceinline__ uint32_t tf_bits32(uint32_t k0, uint32_t k1, uint32_t ctr)
{
    uint32_t k2 = k0 ^ k1 ^ 0x1BD11BDAu;
    uint32_t x0 = k0;          // 0 + k0
    uint32_t x1 = ctr + k1;
#define TF_R(r) { x0 += x1; x1 = __funnelshift_l(x1, x1, (r)); x1 ^= x0; }
    TF_R(13) TF_R(15) TF_R(26) TF_R(6)
    x0 += k1; x1 += k2 + 1u;
    TF_R(17) TF_R(29) TF_R(16) TF_R(24)
    x0 += k2; x1 += k0 + 2u;
    TF_R(13) TF_R(15) TF_R(26) TF_R(6)
    x0 += k0; x1 += k1 + 3u;
    TF_R(17) TF_R(29) TF_R(16) TF_R(24)
    x0 += k1; x1 += k2 + 4u;
    TF_R(13) TF_R(15) TF_R(26) TF_R(6)
    x0 += k2; x1 += k0 + 5u;
#undef TF_R
    return x0 ^ x1;
}

// ======================= kernels ===================================================
__global__ void dq_init()
{
    g_over_cnt  = 0u;
    g_under_cnt = 0u;
}

// Count pass at sigma0 = 0.25: t_max = 31.75, t_min = -32; half-range 15.875 / -16.
__global__ void __launch_bounds__(256) dq_count(const float4* __restrict__ x, int n4)
{
    const float TMAX = 31.75f,  TMIN = -32.0f;
    const float HMAX = 15.875f, HMIN = -16.0f;
    unsigned over = 0u, under = 0u;
    for (int i = blockIdx.x * blockDim.x + threadIdx.x; i < n4;
         i += gridDim.x * blockDim.x) {
        float4 v = x[i];
        over  += (unsigned)(v.x > TMAX) + (unsigned)(v.x < TMIN)
               + (unsigned)(v.y > TMAX) + (unsigned)(v.y < TMIN)
               + (unsigned)(v.z > TMAX) + (unsigned)(v.z < TMIN)
               + (unsigned)(v.w > TMAX) + (unsigned)(v.w < TMIN);
        under += (unsigned)(v.x > HMAX) + (unsigned)(v.x < HMIN)
               + (unsigned)(v.y > HMAX) + (unsigned)(v.y < HMIN)
               + (unsigned)(v.z > HMAX) + (unsigned)(v.z < HMIN)
               + (unsigned)(v.w > HMAX) + (unsigned)(v.w < HMIN);
    }
#pragma unroll
    for (int o = 16; o > 0; o >>= 1) {
        over  += __shfl_down_sync(0xffffffffu, over,  o);
        under += __shfl_down_sync(0xffffffffu, under, o);
    }
    if ((threadIdx.x & 31) == 0 && (over | under)) {
        atomicAdd(&g_over_cnt,  over);
        atomicAdd(&g_under_cnt, under);
    }
}

// Pick sigma exactly as the reference does (float32 fraction compares).
__global__ void dq_config(float nf)
{
    float overf  = (float)g_over_cnt  / nf;
    float underf = (float)g_under_cnt / nf;
    float sigma, inv;
    if (overf > 0.01f)        { sigma = 0.5f;   inv = 2.0f; }
    else if (underf < 0.01f)  { sigma = 0.125f; inv = 8.0f; }
    else                      { sigma = 0.25f;  inv = 4.0f; }
    // t_max = sigma*128 - sigma = sigma*127 (exact);  t_min = -sigma*128
    g_qparams = make_float4(sigma, inv, -sigma * 128.0f, sigma * 127.0f);
}

__device__ __forceinline__ float dq_one(float v, uint32_t bits,
                                        float inv, float sigma,
                                        float tmin, float tmax)
{
    // JAX uniform: bitcast((bits>>9)|0x3f800000) - 1  in [0,1)
    float r = __uint_as_float((bits >> 9) | 0x3f800000u) - 1.0f;
    // v*inv is exact (sigma power of two), so fmaf == (v/sigma) + r bit-exactly
    float q = floorf(fmaf(v, inv, r)) * sigma;
    return fminf(fmaxf(q, tmin), tmax);
}

__global__ void __launch_bounds__(256) dq_quant(const float4* __restrict__ x,
                                                float4* __restrict__ out,
                                                unsigned n4,
                                                uint32_t K0, uint32_t K1)
{
    unsigned i = blockIdx.x * blockDim.x + threadIdx.x;
    if (i >= n4) return;

    float4 p = g_qparams;
    const float sigma = p.x, inv = p.y, tmin = p.z, tmax = p.w;

    float4 v = x[i];
    uint32_t c = i * 4u;

    // 4 independent hash chains -> ILP
    uint32_t b0 = tf_bits32(K0, K1, c + 0u);
    uint32_t b1 = tf_bits32(K0, K1, c + 1u);
    uint32_t b2 = tf_bits32(K0, K1, c + 2u);
    uint32_t b3 = tf_bits32(K0, K1, c + 3u);

    float4 q;
    q.x = dq_one(v.x, b0, inv, sigma, tmin, tmax);
    q.y = dq_one(v.y, b1, inv, sigma, tmin, tmax);
    q.z = dq_one(v.z, b2, inv, sigma, tmin, tmax);
    q.w = dq_one(v.w, b3, inv, sigma, tmin, tmax);

    out[i] = q;
}

// Scalar tail kernels (not exercised for N = 2^27, kept for generality).
__global__ void dq_count_tail(const float* __restrict__ x, int start, int n)
{
    unsigned over = 0u, under = 0u;
    for (int i = start; i < n; i++) {
        float v = x[i];
        over  += (unsigned)(v > 31.75f)  + (unsigned)(v < -32.0f);
        under += (unsigned)(v > 15.875f) + (unsigned)(v < -16.0f);
    }
    if (over)  atomicAdd(&g_over_cnt,  over);
    if (under) atomicAdd(&g_under_cnt, under);
}

__global__ void dq_quant_tail(const float* __restrict__ x, float* __restrict__ out,
                              int start, int n, uint32_t K0, uint32_t K1)
{
    int i = start + blockIdx.x * blockDim.x + threadIdx.x;
    if (i >= n) return;
    float4 p = g_qparams;
    uint32_t b = tf_bits32(K0, K1, (uint32_t)i);
    out[i] = dq_one(x[i], b, p.y, p.x, p.z, p.w);
}

// ======================= host side =================================================
static inline uint32_t h_rotl(uint32_t v, int r) { return (v << r) | (v >> (32 - r)); }

static void host_threefry(uint32_t k0, uint32_t k1, uint32_t x0, uint32_t x1,
                          uint32_t* o0, uint32_t* o1)
{
    uint32_t k2 = k0 ^ k1 ^ 0x1BD11BDAu;
    x0 += k0; x1 += k1;
#define HR(r) { x0 += x1; x1 = h_rotl(x1, (r)); x1 ^= x0; }
    HR(13) HR(15) HR(26) HR(6)
    x0 += k1; x1 += k2 + 1u;
    HR(17) HR(29) HR(16) HR(24)
    x0 += k2; x1 += k0 + 2u;
    HR(13) HR(15) HR(26) HR(6)
    x0 += k0; x1 += k1 + 3u;
    HR(17) HR(29) HR(16) HR(24)
    x0 += k1; x1 += k2 + 4u;
    HR(13) HR(15) HR(26) HR(6)
    x0 += k2; x1 += k0 + 5u;
#undef HR
    *o0 = x0; *o1 = x1;
}

extern "C" void kernel_launch(void* const* d_in, const int* in_sizes, int n_in,
                              void* d_out, int out_size)
{
    const float* x   = (const float*)d_in[0];
    float*       out = (float*)d_out;
    const int n  = in_sizes[0];
    const int n4 = n >> 2;
    const int rem_start = n4 << 2;

    // folded key: fold_in(key(42), 0) = threefry((0,42), (0,0))
    uint32_t fk0, fk1;
    host_threefry(0u, 42u, 0u, 0u, &fk0, &fk1);

    dq_init<<<1, 1>>>();

    int cblocks = (n4 + 255) / 256;
    if (cblocks > 4096) cblocks = 4096;
    if (cblocks < 1)    cblocks = 1;
    if (n4 > 0) dq_count<<<cblocks, 256>>>((const float4*)x, n4);
    if (rem_start < n) dq_count_tail<<<1, 1>>>(x, rem_start, n);

    dq_config<<<1, 1>>>((float)n);

    if (n4 > 0) {
        unsigned qblocks = (unsigned)((n4 + 255) / 256);
        dq_quant<<<qblocks, 256>>>((const float4*)x, (float4*)out,
                                   (unsigned)n4, fk0, fk1);
    }
    if (rem_start < n) {
        int tn = n - rem_start;
        dq_quant_tail<<<(tn + 255) / 256, 256>>>(x, out, rem_start, n, fk0, fk1);
    }
}

// round 3
// speedup vs baseline: 1.0700x; 1.0700x over previous
#include <cuda_runtime.h>
#include <stdint.h>

// ======================= device globals (scratch; no allocs) =======================
__device__ unsigned int g_over_cnt;
__device__ unsigned int g_under_cnt;
__device__ float4       g_qparams;   // {sigma, 1/sigma, t_min, t_max}
__device__ int          g_fix;       // 1 if speculation (sigma=0.125) was wrong

// ======================= threefry2x32 (20 rounds, Random123/JAX) ===================
// Counter = (0, ctr); returns o0 ^ o1 (JAX partitionable 32-bit bits).
// Key-schedule injection constants precomputed on host and passed in.
__device__ __forceinline__ uint32_t tf_bits32(
    uint32_t ctr,
    uint32_t k0, uint32_t k1, uint32_t k2,
    uint32_t k2p1, uint32_t k0p2, uint32_t k1p3, uint32_t k2p4, uint32_t k0p5)
{
    uint32_t x0 = k0;          // 0 + k0
    uint32_t x1 = ctr + k1;
#define TF_R(r) { x0 += x1; x1 = __funnelshift_l(x1, x1, (r)); x1 ^= x0; }
    TF_R(13) TF_R(15) TF_R(26) TF_R(6)
    x0 += k1; x1 += k2p1;
    TF_R(17) TF_R(29) TF_R(16) TF_R(24)
    x0 += k2; x1 += k0p2;
    TF_R(13) TF_R(15) TF_R(26) TF_R(6)
    x0 += k0; x1 += k1p3;
    TF_R(17) TF_R(29) TF_R(16) TF_R(24)
    x0 += k1; x1 += k2p4;
    TF_R(13) TF_R(15) TF_R(26) TF_R(6)
    x0 += k2; x1 += k0p5;
#undef TF_R
    return x0 ^ x1;
}

// JAX uniform in [0,1): bitcast((bits>>9)|0x3f800000)-1 == (float)(bits>>9) * 2^-23
// (m < 2^23 is exact in f32; power-of-two scale exact; subtraction was exact by
//  Sterbenz). Uses I2F (conversion pipe) + FMUL (fma pipe) instead of LOP3 (alu).
__device__ __forceinline__ float tf_uniform(uint32_t bits)
{
    return (float)(bits >> 9) * 0x1p-23f;
}

// Speculative quantize with sigma = 0.125 (compile-time constants).
__device__ __forceinline__ float dq_spec_one(float v, uint32_t bits)
{
    float r = tf_uniform(bits);
    // v*8 is exact, so fmaf == (v/sigma)+r with one rounding, matching XLA
    float q = floorf(fmaf(v, 8.0f, r)) * 0.125f;
    return fminf(fmaxf(q, -16.0f), 15.875f);
}

// Generic quantize with runtime params (fixup path only).
__device__ __forceinline__ float dq_gen_one(float v, uint32_t bits,
                                            float inv, float sigma,
                                            float tmin, float tmax)
{
    float r = tf_uniform(bits);
    float q = floorf(fmaf(v, inv, r)) * sigma;
    return fminf(fmaxf(q, tmin), tmax);
}

// ======================= kernels ===================================================
__global__ void dq_init()
{
    g_over_cnt  = 0u;
    g_under_cnt = 0u;
    g_fix       = 0;
}

// Fused: count overflow/underflow at sigma0=0.25 AND write speculative output
// quantized with sigma=0.125.  Midpoint-shifted abs tests:
//   over : v>31.75  || v<-32  <=> |v+0.125 | > 31.875
//   under: v>15.875 || v<-16  <=> |v+0.0625| > 15.9375
__global__ void __launch_bounds__(256) dq_main(
    const float4* __restrict__ x, float4* __restrict__ out, unsigned n4,
    uint32_t k0, uint32_t k1, uint32_t k2,
    uint32_t k2p1, uint32_t k0p2, uint32_t k1p3, uint32_t k2p4, uint32_t k0p5)
{
    unsigned i = blockIdx.x * blockDim.x + threadIdx.x;
    unsigned over = 0u, under = 0u;

    if (i < n4) {
        float4 v = x[i];

        over  += (unsigned)(fabsf(v.x + 0.125f)  > 31.875f);
        over  += (unsigned)(fabsf(v.y + 0.125f)  > 31.875f);
        over  += (unsigned)(fabsf(v.z + 0.125f)  > 31.875f);
        over  += (unsigned)(fabsf(v.w + 0.125f)  > 31.875f);
        under += (unsigned)(fabsf(v.x + 0.0625f) > 15.9375f);
        under += (unsigned)(fabsf(v.y + 0.0625f) > 15.9375f);
        under += (unsigned)(fabsf(v.z + 0.0625f) > 15.9375f);
        under += (unsigned)(fabsf(v.w + 0.0625f) > 15.9375f);

        uint32_t c = i * 4u;
        uint32_t b0 = tf_bits32(c + 0u, k0, k1, k2, k2p1, k0p2, k1p3, k2p4, k0p5);
        uint32_t b1 = tf_bits32(c + 1u, k0, k1, k2, k2p1, k0p2, k1p3, k2p4, k0p5);
        uint32_t b2 = tf_bits32(c + 2u, k0, k1, k2, k2p1, k0p2, k1p3, k2p4, k0p5);
        uint32_t b3 = tf_bits32(c + 3u, k0, k1, k2, k2p1, k0p2, k1p3, k2p4, k0p5);

        float4 q;
        q.x = dq_spec_one(v.x, b0);
        q.y = dq_spec_one(v.y, b1);
        q.z = dq_spec_one(v.z, b2);
        q.w = dq_spec_one(v.w, b3);
        out[i] = q;
    }

    // Warp reduce (all threads in the warp reach here; inactive ones hold 0).
#pragma unroll
    for (int o = 16; o > 0; o >>= 1) {
        over  += __shfl_down_sync(0xffffffffu, over,  o);
        under += __shfl_down_sync(0xffffffffu, under, o);
    }
    if ((threadIdx.x & 31) == 0 && (over | under)) {
        atomicAdd(&g_over_cnt,  over);
        atomicAdd(&g_under_cnt, under);
    }
}

// Scalar tail: count + speculative quant (only if n % 4 != 0).
__global__ void dq_tail(const float* __restrict__ x, float* __restrict__ out,
                        int start, int n,
                        uint32_t k0, uint32_t k1, uint32_t k2,
                        uint32_t k2p1, uint32_t k0p2, uint32_t k1p3,
                        uint32_t k2p4, uint32_t k0p5)
{
    unsigned over = 0u, under = 0u;
    for (int i = start; i < n; i++) {
        float v = x[i];
        over  += (unsigned)(fabsf(v + 0.125f)  > 31.875f);
        under += (unsigned)(fabsf(v + 0.0625f) > 15.9375f);
        uint32_t b = tf_bits32((uint32_t)i, k0, k1, k2, k2p1, k0p2, k1p3, k2p4, k0p5);
        out[i] = dq_spec_one(v, b);
    }
    if (over)  atomicAdd(&g_over_cnt,  over);
    if (under) atomicAdd(&g_under_cnt, under);
}

// Decision, exactly mirroring the reference float32 math.
__global__ void dq_config(float nf)
{
    float overf  = (float)g_over_cnt  / nf;
    float underf = (float)g_under_cnt / nf;
    float sigma, inv;
    if (overf > 0.01f)        { sigma = 0.5f;   inv = 2.0f; }
    else if (underf < 0.01f)  { sigma = 0.125f; inv = 8.0f; }
    else                      { sigma = 0.25f;  inv = 4.0f; }
    g_qparams = make_float4(sigma, inv, -sigma * 128.0f, sigma * 127.0f);
    g_fix = (sigma != 0.125f) ? 1 : 0;
}

// Conditional fixup: if speculation was wrong, re-quantize everything with the
// chosen sigma. Early-exits (~µs) when speculation was right.
__global__ void __launch_bounds__(256) dq_fixup(
    const float* __restrict__ x, float* __restrict__ out, int n,
    uint32_t k0, uint32_t k1, uint32_t k2,
    uint32_t k2p1, uint32_t k0p2, uint32_t k1p3, uint32_t k2p4, uint32_t k0p5)
{
    if (!g_fix) return;
    float4 p = g_qparams;
    const float sigma = p.x, inv = p.y, tmin = p.z, tmax = p.w;
    for (int i = blockIdx.x * blockDim.x + threadIdx.x; i < n;
         i += gridDim.x * blockDim.x) {
        uint32_t b = tf_bits32((uint32_t)i, k0, k1, k2, k2p1, k0p2, k1p3, k2p4, k0p5);
        out[i] = dq_gen_one(x[i], b, inv, sigma, tmin, tmax);
    }
}

// ======================= host side =================================================
static inline uint32_t h_rotl(uint32_t v, int r) { return (v << r) | (v >> (32 - r)); }

static void host_threefry(uint32_t k0, uint32_t k1, uint32_t x0, uint32_t x1,
                          uint32_t* o0, uint32_t* o1)
{
    uint32_t k2 = k0 ^ k1 ^ 0x1BD11BDAu;
    x0 += k0; x1 += k1;
#define HR(r) { x0 += x1; x1 = h_rotl(x1, (r)); x1 ^= x0; }
    HR(13) HR(15) HR(26) HR(6)
    x0 += k1; x1 += k2 + 1u;
    HR(17) HR(29) HR(16) HR(24)
    x0 += k2; x1 += k0 + 2u;
    HR(13) HR(15) HR(26) HR(6)
    x0 += k0; x1 += k1 + 3u;
    HR(17) HR(29) HR(16) HR(24)
    x0 += k1; x1 += k2 + 4u;
    HR(13) HR(15) HR(26) HR(6)
    x0 += k2; x1 += k0 + 5u;
#undef HR
    *o0 = x0; *o1 = x1;
}

extern "C" void kernel_launch(void* const* d_in, const int* in_sizes, int n_in,
                              void* d_out, int out_size)
{
    const float* x   = (const float*)d_in[0];
    float*       out = (float*)d_out;
    const int n  = in_sizes[0];
    const int n4 = n >> 2;
    const int rem_start = n4 << 2;

    // folded key: fold_in(key(42), 0) = threefry((0,42), (0,0))
    uint32_t fk0, fk1;
    host_threefry(0u, 42u, 0u, 0u, &fk0, &fk1);
    uint32_t fk2  = fk0 ^ fk1 ^ 0x1BD11BDAu;
    uint32_t k2p1 = fk2 + 1u;
    uint32_t k0p2 = fk0 + 2u;
    uint32_t k1p3 = fk1 + 3u;
    uint32_t k2p4 = fk2 + 4u;
    uint32_t k0p5 = fk0 + 5u;

    dq_init<<<1, 1>>>();

    if (n4 > 0) {
        unsigned blocks = (unsigned)((n4 + 255) / 256);
        dq_main<<<blocks, 256>>>((const float4*)x, (float4*)out, (unsigned)n4,
                                 fk0, fk1, fk2, k2p1, k0p2, k1p3, k2p4, k0p5);
    }
    if (rem_start < n) {
        dq_tail<<<1, 1>>>(x, out, rem_start, n,
                          fk0, fk1, fk2, k2p1, k0p2, k1p3, k2p4, k0p5);
    }

    dq_config<<<1, 1>>>((float)n);

    dq_fixup<<<2048, 256>>>(x, out, n,
                            fk0, fk1, fk2, k2p1, k0p2, k1p3, k2p4, k0p5);
}

// round 7
// speedup vs baseline: 1.2621x; 1.1796x over previous
#include <cuda_runtime.h>
#include <stdint.h>

// ======================= device globals (scratch; no allocs) =======================
__device__ unsigned int g_over_cnt;
__device__ unsigned int g_under_cnt;
__device__ float4       g_qparams;   // {sigma, 1/sigma, t_min, t_max}
__device__ int          g_fix;       // 1 if speculation (sigma=0.125) was wrong

// ======================= threefry2x32 (20 rounds, Random123/JAX) ===================
// Counter = (0, ctr); returns o0 ^ o1 (JAX partitionable 32-bit bits).
__device__ __forceinline__ uint32_t tf_bits32(
    uint32_t ctr,
    uint32_t k0, uint32_t k1, uint32_t k2,
    uint32_t k2p1, uint32_t k0p2, uint32_t k1p3, uint32_t k2p4, uint32_t k0p5)
{
    uint32_t x0 = k0;          // 0 + k0
    uint32_t x1 = ctr + k1;
#define TF_R(r) { x0 += x1; x1 = __funnelshift_l(x1, x1, (r)); x1 ^= x0; }
    TF_R(13) TF_R(15) TF_R(26) TF_R(6)
    x0 += k1; x1 += k2p1;
    TF_R(17) TF_R(29) TF_R(16) TF_R(24)
    x0 += k2; x1 += k0p2;
    TF_R(13) TF_R(15) TF_R(26) TF_R(6)
    x0 += k0; x1 += k1p3;
    TF_R(17) TF_R(29) TF_R(16) TF_R(24)
    x0 += k1; x1 += k2p4;
    TF_R(13) TF_R(15) TF_R(26) TF_R(6)
    x0 += k2; x1 += k0p5;
#undef TF_R
    return x0 ^ x1;
}

// JAX uniform in [0,1): (float)(bits>>9) * 2^-23, bit-exact vs bitcast-or-sub-1.
// bits>>9 done as umulhi (IMAD.HI, fma pipe) instead of SHF (alu pipe).
__device__ __forceinline__ float tf_uniform(uint32_t bits)
{
    return (float)__umulhi(bits, 1u << 23) * 0x1p-23f;
}

// floor + clamp-to-[-128,127] in one conversion op, then scale.
// Exact: clip(floor(t)*s, -128s, 127s) == clamp(floor(t),-128,127)*s for s=2^-k.
__device__ __forceinline__ float dq_floor_sat_scale(float t, float sigma)
{
    int s8;
    asm("cvt.rmi.sat.s8.f32 %0, %1;" : "=r"(s8) : "f"(t));
    float f;
    asm("cvt.rn.f32.s8 %0, %1;" : "=f"(f) : "r"(s8));
    return f * sigma;
}

// ======================= kernels ===================================================
__global__ void dq_init()
{
    g_over_cnt  = 0u;
    g_under_cnt = 0u;
    g_fix       = 0;
}

// Fused: speculative quantize (sigma=0.125) + overflow/underflow counting.
// Fast-path count test: under condition (8v>127 || 8v<-128) implies |t|>127
// where t = fma(v,8,r), r in [0,1). |t|>127 is a conservative superset; the
// exact shifted-abs count runs only in the (warp-converged) rare path.
//   over : v>31.75  || v<-32  <=> |v+0.125 | > 31.875
//   under: v>15.875 || v<-16  <=> |v+0.0625| > 15.9375
__global__ void __launch_bounds__(256) dq_main(
    const float4* __restrict__ x, float4* __restrict__ out, unsigned n4,
    uint32_t k0, uint32_t k1, uint32_t k2,
    uint32_t k2p1, uint32_t k0p2, uint32_t k1p3, uint32_t k2p4, uint32_t k0p5)
{
    unsigned i = blockIdx.x * blockDim.x + threadIdx.x;
    unsigned over = 0u, under = 0u;
    bool dirty = false;

    bool active = (i < n4);
    if (active) {
        float4 v = x[i];
        uint32_t c = i * 4u;

        uint32_t b0 = tf_bits32(c + 0u, k0, k1, k2, k2p1, k0p2, k1p3, k2p4, k0p5);
        uint32_t b1 = tf_bits32(c + 1u, k0, k1, k2, k2p1, k0p2, k1p3, k2p4, k0p5);
        uint32_t b2 = tf_bits32(c + 2u, k0, k1, k2, k2p1, k0p2, k1p3, k2p4, k0p5);
        uint32_t b3 = tf_bits32(c + 3u, k0, k1, k2, k2p1, k0p2, k1p3, k2p4, k0p5);

        float t0 = fmaf(v.x, 8.0f, tf_uniform(b0));
        float t1 = fmaf(v.y, 8.0f, tf_uniform(b1));
        float t2 = fmaf(v.z, 8.0f, tf_uniform(b2));
        float t3 = fmaf(v.w, 8.0f, tf_uniform(b3));

        float4 q;
        q.x = dq_floor_sat_scale(t0, 0.125f);
        q.y = dq_floor_sat_scale(t1, 0.125f);
        q.z = dq_floor_sat_scale(t2, 0.125f);
        q.w = dq_floor_sat_scale(t3, 0.125f);
        out[i] = q;

        // conservative fast test (superset of the under condition)
        float m = fmaxf(fmaxf(fabsf(t0), fabsf(t1)), fmaxf(fabsf(t2), fabsf(t3)));
        bool maybe = (m > 127.0f);

        if (__any_sync(0xffffffffu, maybe)) {
            dirty = true;   // warp-uniform
            over  += (unsigned)(fabsf(v.x + 0.125f)  > 31.875f);
            over  += (unsigned)(fabsf(v.y + 0.125f)  > 31.875f);
            over  += (unsigned)(fabsf(v.z + 0.125f)  > 31.875f);
            over  += (unsigned)(fabsf(v.w + 0.125f)  > 31.875f);
            under += (unsigned)(fabsf(v.x + 0.0625f) > 15.9375f);
            under += (unsigned)(fabsf(v.y + 0.0625f) > 15.9375f);
            under += (unsigned)(fabsf(v.z + 0.0625f) > 15.9375f);
            under += (unsigned)(fabsf(v.w + 0.0625f) > 15.9375f);
        }
    } else {
        // keep warp convergent for the votes above: inactive threads vote false
        if (__any_sync(0xffffffffu, false)) { dirty = true; }
    }

    if (dirty) {   // warp-uniform
#pragma unroll
        for (int o = 16; o > 0; o >>= 1) {
            over  += __shfl_down_sync(0xffffffffu, over,  o);
            under += __shfl_down_sync(0xffffffffu, under, o);
        }
        if ((threadIdx.x & 31) == 0 && (over | under)) {
            atomicAdd(&g_over_cnt,  over);
            atomicAdd(&g_under_cnt, under);
        }
    }
}

// Scalar tail: exact count + speculative quant (only if n % 4 != 0).
__global__ void dq_tail(const float* __restrict__ x, float* __restrict__ out,
                        int start, int n,
                        uint32_t k0, uint32_t k1, uint32_t k2,
                        uint32_t k2p1, uint32_t k0p2, uint32_t k1p3,
                        uint32_t k2p4, uint32_t k0p5)
{
    unsigned over = 0u, under = 0u;
    for (int i = start; i < n; i++) {
        float v = x[i];
        over  += (unsigned)(fabsf(v + 0.125f)  > 31.875f);
        under += (unsigned)(fabsf(v + 0.0625f) > 15.9375f);
        uint32_t b = tf_bits32((uint32_t)i, k0, k1, k2, k2p1, k0p2, k1p3, k2p4, k0p5);
        float t = fmaf(v, 8.0f, tf_uniform(b));
        out[i] = dq_floor_sat_scale(t, 0.125f);
    }
    if (over)  atomicAdd(&g_over_cnt,  over);
    if (under) atomicAdd(&g_under_cnt, under);
}

// Decision, mirroring the reference float32 math exactly.
__global__ void dq_config(float nf)
{
    float overf  = (float)g_over_cnt  / nf;
    float underf = (float)g_under_cnt / nf;
    float sigma, inv;
    if (overf > 0.01f)        { sigma = 0.5f;   inv = 2.0f; }
    else if (underf < 0.01f)  { sigma = 0.125f; inv = 8.0f; }
    else                      { sigma = 0.25f;  inv = 4.0f; }
    g_qparams = make_float4(sigma, inv, -sigma * 128.0f, sigma * 127.0f);
    g_fix = (sigma != 0.125f) ? 1 : 0;
}

// Conditional fixup: re-quantize with the chosen sigma iff speculation was wrong.
// The s8 saturation range [-128,127] is the clip range for every sigma choice.
__global__ void __launch_bounds__(256) dq_fixup(
    const float* __restrict__ x, float* __restrict__ out, int n,
    uint32_t k0, uint32_t k1, uint32_t k2,
    uint32_t k2p1, uint32_t k0p2, uint32_t k1p3, uint32_t k2p4, uint32_t k0p5)
{
    if (!g_fix) return;
    float4 p = g_qparams;
    const float sigma = p.x, inv = p.y;
    for (int i = blockIdx.x * blockDim.x + threadIdx.x; i < n;
         i += gridDim.x * blockDim.x) {
        uint32_t b = tf_bits32((uint32_t)i, k0, k1, k2, k2p1, k0p2, k1p3, k2p4, k0p5);
        float t = fmaf(x[i], inv, tf_uniform(b));
        out[i] = dq_floor_sat_scale(t, sigma);
    }
}

// ======================= host side =================================================
static inline uint32_t h_rotl(uint32_t v, int r) { return (v << r) | (v >> (32 - r)); }

static void host_threefry(uint32_t k0, uint32_t k1, uint32_t x0, uint32_t x1,
                          uint32_t* o0, uint32_t* o1)
{
    uint32_t k2 = k0 ^ k1 ^ 0x1BD11BDAu;
    x0 += k0; x1 += k1;
#define HR(r) { x0 += x1; x1 = h_rotl(x1, (r)); x1 ^= x0; }
    HR(13) HR(15) HR(26) HR(6)
    x0 += k1; x1 += k2 + 1u;
    HR(17) HR(29) HR(16) HR(24)
    x0 += k2; x1 += k0 + 2u;
    HR(13) HR(15) HR(26) HR(6)
    x0 += k0; x1 += k1 + 3u;
    HR(17) HR(29) HR(16) HR(24)
    x0 += k1; x1 += k2 + 4u;
    HR(13) HR(15) HR(26) HR(6)
    x0 += k2; x1 += k0 + 5u;
#undef HR
    *o0 = x0; *o1 = x1;
}

extern "C" void kernel_launch(void* const* d_in, const int* in_sizes, int n_in,
                              void* d_out, int out_size)
{
    const float* x   = (const float*)d_in[0];
    float*       out = (float*)d_out;
    const int n  = in_sizes[0];
    const int n4 = n >> 2;
    const int rem_start = n4 << 2;

    // folded key: fold_in(key(42), 0) = threefry((0,42), (0,0))
    uint32_t fk0, fk1;
    host_threefry(0u, 42u, 0u, 0u, &fk0, &fk1);
    uint32_t fk2  = fk0 ^ fk1 ^ 0x1BD11BDAu;
    uint32_t k2p1 = fk2 + 1u;
    uint32_t k0p2 = fk0 + 2u;
    uint32_t k1p3 = fk1 + 3u;
    uint32_t k2p4 = fk2 + 4u;
    uint32_t k0p5 = fk0 + 5u;

    dq_init<<<1, 1>>>();

    if (n4 > 0) {
        unsigned blocks = (unsigned)((n4 + 255) / 256);
        dq_main<<<blocks, 256>>>((const float4*)x, (float4*)out, (unsigned)n4,
                                 fk0, fk1, fk2, k2p1, k0p2, k1p3, k2p4, k0p5);
    }
    if (rem_start < n) {
        dq_tail<<<1, 1>>>(x, out, rem_start, n,
                          fk0, fk1, fk2, k2p1, k0p2, k1p3, k2p4, k0p5);
    }

    dq_config<<<1, 1>>>((float)n);

    dq_fixup<<<2048, 256>>>(x, out, n,
                            fk0, fk1, fk2, k2p1, k0p2, k1p3, k2p4, k0p5);
}